// round 12
// baseline (speedup 1.0000x reference)
#include <cuda_runtime.h>
#include <stdint.h>

// Problem constants (fixed by the reference problem definition)
#define FEAT_DIM 128
#define BATCH    4
#define NY       512
#define NX       512
#define NYNX     (NY * NX)
#define NPIX     (BATCH * NYNX)      // 1,048,576

#define XT     128     // x-tile per gather tile (4 stages of 32)
#define SPX    32      // pixels per stage
#define NBUF   3       // ring buffers: smem ~50KB -> 4 blocks/SM
#define NTH    512     // 16 warps
#define NTILES (BATCH * NY * (NX / XT))   // 8192
#define NBLK   576     // persistent blocks: 4/SM x 144 (<=148/152 SMs, all resident)

// 4 MB scratch: winner map. INVARIANT: all-zero on entry to kernel_launch.
//  - zero at module load; phase 1 writes (voxel_index + 1) via atomicMax
//    (last-write-wins == max index); phase 2 restores consumed entries to 0.
__device__ int g_map[NPIX];
// Monotone arrival counter for the device-wide barrier. Never reset:
// each call adds exactly NBLK; target = old - old%NBLK + NBLK (replay-safe).
__device__ unsigned g_bar;

// ---------------------------------------------------------------------------
// cp.async helpers: 16B global->shared, src_size=0 => zero-fill (empty pixels)
// ---------------------------------------------------------------------------
__device__ __forceinline__ uint32_t smem_u32(const void* p) {
    return (uint32_t)__cvta_generic_to_shared(p);
}
__device__ __forceinline__ void cp_async16(uint32_t dst, const void* src, int src_size) {
    asm volatile("cp.async.cg.shared.global [%0], [%1], 16, %2;\n"
                 :: "r"(dst), "l"(src), "r"(src_size));
}
__device__ __forceinline__ void cp_commit() {
    asm volatile("cp.async.commit_group;\n" ::: "memory");
}
template <int N>
__device__ __forceinline__ void cp_wait() {
    asm volatile("cp.async.wait_group %0;\n" :: "n"(N) : "memory");
}

// ---------------------------------------------------------------------------
// Gather tile helpers (R11 plateau body: 112.5us, DRAM 73% -- at HBM ceiling)
// Swizzle: P(xl, c) = xl*128 + ((c>>2 ^ xl) << 2) + (c&3), xl = x % 32.
// ---------------------------------------------------------------------------
__device__ __forceinline__ void fill_stage(const float* __restrict__ feat,
                                           float* __restrict__ buf,
                                           const int* __restrict__ vidx,
                                           int s, int warp, int lane) {
    #pragma unroll
    for (int m = 0; m < 2; m++) {
        int xl = warp * 2 + m;                     // 0..31 within stage
        int v  = vidx[s * SPX + xl];
        uint32_t dst = smem_u32(&buf[xl * FEAT_DIM + ((lane ^ xl) << 2)]);
        const float* src = feat + (size_t)(v < 0 ? 0 : v) * FEAT_DIM + lane * 4;
        cp_async16(dst, src, v < 0 ? 0 : 16);      // zfill empties
    }
    cp_commit();
}

__device__ __forceinline__ void drain_stage(float* __restrict__ out,
                                            const float* __restrict__ buf,
                                            size_t pixbase, int s,
                                            int warp, int lane) {
    #pragma unroll
    for (int m = 0; m < 2; m++) {
        int q = warp * 2 + m;                      // channel quad 0..31
        float4 val = *reinterpret_cast<const float4*>(
            &buf[lane * FEAT_DIM + ((q ^ lane) << 2)]);     // LDS.128
        size_t o = pixbase + (size_t)(4 * q) * NYNX + s * SPX + lane;
        __stcs(out + o,            val.x);         // 4 x 128B coalesced STG
        __stcs(out + o +     NYNX, val.y);
        __stcs(out + o + 2 * NYNX, val.z);
        __stcs(out + o + 3 * NYNX, val.w);
    }
}

// ---------------------------------------------------------------------------
// Fused persistent kernel:
//   phase 1: strided atomicMax winner-map over all voxels
//   device-wide barrier (all NBLK blocks co-resident by construction)
//   phase 2: each block loops over gather tiles (tile += NBLK)
// ---------------------------------------------------------------------------
__global__ __launch_bounds__(NTH, 4)
void k_fused(const float* __restrict__ feat,
             const int* __restrict__ coors, int n,
             float* __restrict__ out) {
    __shared__ float buf[NBUF][SPX * FEAT_DIM];    // 3 x 16 KB ring
    __shared__ int   vidx[XT];

    int blk  = blockIdx.x;
    int t    = threadIdx.x, warp = t >> 5, lane = t & 31;

    // ---- Phase 1: winner per pixel ----
    for (int j = blk * NTH + t; j < n; j += NBLK * NTH) {
        int4 c = reinterpret_cast<const int4*>(coors)[j];
        atomicMax(&g_map[c.x * NYNX + c.z * NX + c.w], j + 1);
    }

    // ---- Device-wide barrier (monotone counter, replay-safe) ----
    if (t == 0) {
        __threadfence();
        unsigned old = atomicAdd(&g_bar, 1u);
        unsigned target = old - (old % NBLK) + NBLK;
        while ((int)(*(volatile unsigned*)&g_bar - target) < 0)
            __nanosleep(128);
        __threadfence();
    }
    __syncthreads();

    // ---- Phase 2: gather tiles ----
    for (int tile = blk; tile < NTILES; tile += NBLK) {
        __syncthreads();                 // prev tile's drains done before reuse

        int xt = tile & (NX / XT - 1);   // 0..3
        int y  = (tile >> 2) & (NY - 1); // 0..511
        int b  = tile >> 11;             // 0..3
        int x0 = xt * XT;

        if (t < XT) {
            int idx = b * NYNX + y * NX + x0 + t;
            int v = g_map[idx];
            vidx[t] = v - 1;             // -1 if empty
            if (v) g_map[idx] = 0;       // restore all-zero invariant
        }
        __syncthreads();

        // Prologue: fill stages 0..2 into ring slots 0..2
        #pragma unroll
        for (int s = 0; s < NBUF; s++)
            fill_stage(feat, buf[s], vidx, s, warp, lane);

        size_t pixbase = (size_t)b * FEAT_DIM * NYNX + (size_t)y * NX + x0;

        // s=0: pending {0,1,2}; need 0 -> wait<2>
        cp_wait<2>();
        __syncthreads();
        drain_stage(out, buf[0], pixbase, 0, warp, lane);
        __syncthreads();                               // slot 0 free
        fill_stage(feat, buf[0], vidx, 3, warp, lane); // stage 3 -> slot 0

        // s=1: pending {1,2,3}; need 1 -> wait<2>
        cp_wait<2>();
        __syncthreads();
        drain_stage(out, buf[1], pixbase, 1, warp, lane);

        // s=2: pending {2,3}; need 2 -> wait<1>
        cp_wait<1>();
        __syncthreads();
        drain_stage(out, buf[2], pixbase, 2, warp, lane);

        // s=3: pending {3}; -> wait<0>
        cp_wait<0>();
        __syncthreads();
        drain_stage(out, buf[0], pixbase, 3, warp, lane);
    }
}

// ---------------------------------------------------------------------------
extern "C" void kernel_launch(void* const* d_in, const int* in_sizes, int n_in,
                              void* d_out, int out_size) {
    const float* feat  = (const float*)d_in[0];
    const int*   coors = (const int*)d_in[1];
    float*       out   = (float*)d_out;

    int n = in_sizes[0] / FEAT_DIM;   // number of voxels

    k_fused<<<NBLK, NTH>>>(feat, coors, n, out);
}

// round 13
// speedup vs baseline: 1.1593x; 1.1593x over previous
#include <cuda_runtime.h>
#include <stdint.h>

// Problem constants (fixed by the reference problem definition)
#define FEAT_DIM 128
#define BATCH    4
#define NY       512
#define NX       512
#define NYNX     (NY * NX)
#define NPIX     (BATCH * NYNX)      // 1,048,576

#define XT    128      // x-tile per block (4 stages of 32)
#define SPX   32       // pixels per stage
#define NBUF  3        // ring buffers: smem ~50KB -> 4 blocks/SM = 64 warps
#define NTH   512      // 16 warps

// 4 MB scratch: winner map. INVARIANT: all-zero on entry to kernel_launch.
//  - zero at module load (device globals are zero-initialized)
//  - k_argmax writes (voxel_index + 1) via atomicMax (last-write-wins == max idx)
//  - k_gather restores every nonzero entry it consumed back to 0
__device__ int g_map[NPIX];

// ---------------------------------------------------------------------------
// cp.async helpers: 16B global->shared, src_size=0 => zero-fill (empty pixels)
// ---------------------------------------------------------------------------
__device__ __forceinline__ uint32_t smem_u32(const void* p) {
    return (uint32_t)__cvta_generic_to_shared(p);
}
__device__ __forceinline__ void cp_async16(uint32_t dst, const void* src, int src_size) {
    asm volatile("cp.async.cg.shared.global [%0], [%1], 16, %2;\n"
                 :: "r"(dst), "l"(src), "r"(src_size));
}
__device__ __forceinline__ void cp_commit() {
    asm volatile("cp.async.commit_group;\n" ::: "memory");
}
template <int N>
__device__ __forceinline__ void cp_wait() {
    asm volatile("cp.async.wait_group %0;\n" :: "n"(N) : "memory");
}

// ---------------------------------------------------------------------------
// Kernel 1: winner per pixel.  coors: [N,4] int32 (b, z, y, x)
// 512-thread blocks, 2 voxels/thread with BOTH loads issued before either
// atomic (atomicMax result unused -> RED, fire-and-forget). __ldcs: coors is
// touch-once, keep L2 clean for the gather's feat reads.
// ---------------------------------------------------------------------------
__global__ __launch_bounds__(512)
void k_argmax_map(const int* __restrict__ coors, int n) {
    int i = (blockIdx.x * blockDim.x + threadIdx.x) * 2;
    if (i + 1 < n) {
        int4 c0 = __ldcs(reinterpret_cast<const int4*>(coors) + i);
        int4 c1 = __ldcs(reinterpret_cast<const int4*>(coors) + i + 1);
        atomicMax(&g_map[c0.x * NYNX + c0.z * NX + c0.w], i + 1);
        atomicMax(&g_map[c1.x * NYNX + c1.z * NX + c1.w], i + 2);
    } else if (i < n) {
        int4 c0 = __ldcs(reinterpret_cast<const int4*>(coors) + i);
        atomicMax(&g_map[c0.x * NYNX + c0.z * NX + c0.w], i + 1);
    }
    cudaTriggerProgrammaticLaunchCompletion();
}

// ---------------------------------------------------------------------------
// Kernel 2: gather + transpose (R11 plateau kernel: 112.5us, DRAM 73.7% --
// at the HBM mixed read/write ceiling; 4 configs confirmed).
// PDL: blocks become resident during k_argmax; cudaGridDependencySynchronize
// gates the g_map read.
// 128-pixel x-tile, 4 stages through a 3-buffer cp.async ring.
// Swizzle: P(xl, c) = xl*128 + ((c>>2 ^ xl) << 2) + (c&3), xl = x % 32.
// ---------------------------------------------------------------------------
__device__ __forceinline__ void fill_stage(const float* __restrict__ feat,
                                           float* __restrict__ buf,
                                           const int* __restrict__ vidx,
                                           int s, int warp, int lane) {
    #pragma unroll
    for (int m = 0; m < 2; m++) {
        int xl = warp * 2 + m;                     // 0..31 within stage
        int v  = vidx[s * SPX + xl];
        uint32_t dst = smem_u32(&buf[xl * FEAT_DIM + ((lane ^ xl) << 2)]);
        const float* src = feat + (size_t)(v < 0 ? 0 : v) * FEAT_DIM + lane * 4;
        cp_async16(dst, src, v < 0 ? 0 : 16);      // zfill empties
    }
    cp_commit();
}

__device__ __forceinline__ void drain_stage(float* __restrict__ out,
                                            const float* __restrict__ buf,
                                            size_t pixbase, int s,
                                            int warp, int lane) {
    #pragma unroll
    for (int m = 0; m < 2; m++) {
        int q = warp * 2 + m;                      // channel quad 0..31
        float4 val = *reinterpret_cast<const float4*>(
            &buf[lane * FEAT_DIM + ((q ^ lane) << 2)]);     // LDS.128
        size_t o = pixbase + (size_t)(4 * q) * NYNX + s * SPX + lane;
        __stcs(out + o,            val.x);         // 4 x 128B coalesced STG
        __stcs(out + o +     NYNX, val.y);
        __stcs(out + o + 2 * NYNX, val.z);
        __stcs(out + o + 3 * NYNX, val.w);
    }
}

__global__ __launch_bounds__(NTH, 4)
void k_gather(const float* __restrict__ feat, float* __restrict__ out) {
    __shared__ float buf[NBUF][SPX * FEAT_DIM];    // 3 x 16 KB ring
    __shared__ int   vidx[XT];                     // 512 B

    int blk = blockIdx.x;              // 0 .. BATCH*NY*(NX/XT)-1
    int xt  = blk & (NX / XT - 1);     // 0..3
    int y   = (blk >> 2) & (NY - 1);   // 0..511
    int b   = blk >> 11;               // 0..3
    int x0  = xt * XT;

    int t = threadIdx.x, warp = t >> 5, lane = t & 31;

    // Wait for k_argmax to finish before touching g_map (PDL edge).
    cudaGridDependencySynchronize();

    if (t < XT) {
        int idx = b * NYNX + y * NX + x0 + t;
        int v = g_map[idx];
        vidx[t] = v - 1;               // -1 if empty
        if (v) g_map[idx] = 0;         // restore all-zero invariant
    }
    __syncthreads();

    // Prologue: fill stages 0..2 into ring slots 0..2
    #pragma unroll
    for (int s = 0; s < NBUF; s++)
        fill_stage(feat, buf[s], vidx, s, warp, lane);

    size_t pixbase = (size_t)b * FEAT_DIM * NYNX + (size_t)y * NX + x0;

    // s=0: groups pending {0,1,2}; need 0 -> wait<2>
    cp_wait<2>();
    __syncthreads();
    drain_stage(out, buf[0], pixbase, 0, warp, lane);
    __syncthreads();                               // slot 0 free
    fill_stage(feat, buf[0], vidx, 3, warp, lane); // stage 3 -> slot 0

    // s=1: pending {1,2,3}; need 1 -> wait<2>
    cp_wait<2>();
    __syncthreads();
    drain_stage(out, buf[1], pixbase, 1, warp, lane);

    // s=2: pending {2,3}; need 2 -> wait<1>
    cp_wait<1>();
    __syncthreads();
    drain_stage(out, buf[2], pixbase, 2, warp, lane);

    // s=3: pending {3}; -> wait<0>
    cp_wait<0>();
    __syncthreads();
    drain_stage(out, buf[0], pixbase, 3, warp, lane);
}

// ---------------------------------------------------------------------------
extern "C" void kernel_launch(void* const* d_in, const int* in_sizes, int n_in,
                              void* d_out, int out_size) {
    const float* feat  = (const float*)d_in[0];
    const int*   coors = (const int*)d_in[1];
    float*       out   = (float*)d_out;

    int n = in_sizes[0] / FEAT_DIM;   // number of voxels

    // 1) winner per pixel (map is all-zero by invariant)
    k_argmax_map<<<(n / 2 + 511) / 512, 512>>>(coors, n);

    // 2) gather, launched with PDL so its blocks spin up under k_argmax.
    cudaLaunchConfig_t cfg = {};
    cfg.gridDim  = dim3(BATCH * NY * (NX / XT));
    cfg.blockDim = dim3(NTH);
    cfg.stream   = 0;
    cudaLaunchAttribute attr[1];
    attr[0].id = cudaLaunchAttributeProgrammaticStreamSerialization;
    attr[0].val.programmaticStreamSerializationAllowed = 1;
    cfg.attrs    = attr;
    cfg.numAttrs = 1;
    cudaLaunchKernelEx(&cfg, k_gather, feat, out);
}